// round 17
// baseline (speedup 1.0000x reference)
#include <cuda_runtime.h>

#define BB 2
#define NN 40000
#define MM 40000
#define PP 128
#define KK 32
#define KC 4
#define FD 128
#define NQ2 (BB*PP*KK)       /* 8192 */
#define GG 32
#define NCELLS (GG*GG*GG)
#define HH (1.0f/GG)
#define CAPC 16              /* slots per cell */
#define CAP32 2048
#define CAP2 1024            /* compacted-candidate capacity */
#define NCTA_F (NQ2/8)       /* 1024 CTAs in fused kernel */
#define NPQ (BB*PP)          /* 256 parent queries */
#define FINF 3.402823466e38f

// ---------------- device scratch (no allocations allowed) ----------------
// noisy counts | clean counts | NPQ flags | noisyCtr | cleanCtr  (one memset)
__device__ int    g_cnt[2*BB*NCELLS + NPQ + 2];
__device__ float4 g_slotN[BB*NCELLS*CAPC];
__device__ float4 g_slotC[BB*NCELLS*CAPC];
__device__ float4 g_f4[NQ2];             // KNN-32 neighbor coords
__device__ float4 g_q4[NPQ];             // sampled query points
__device__ float4 g_c4[NPQ];             // noisy_feat @ Wc
__device__ unsigned long long g_acc;
__device__ unsigned int g_done;

__device__ __forceinline__ int cell_of(float x, float y, float z) {
    int cx = min(max((int)(x * GG), 0), GG-1);
    int cy = min(max((int)(y * GG), 0), GG-1);
    int cz = min(max((int)(z * GG), 0), GG-1);
    return (cz*GG + cy)*GG + cx;
}

// Squared lower bound on distance to any point OUTSIDE the examined box
// [c-r, c+r]^3; faces at/beyond the grid wall contribute nothing.
__device__ __forceinline__ float ring_T(float qx, float qy, float qz,
                                        int cx, int cy, int cz, int r) {
    float m = FINF;
    if (cx - r > 0)      m = fminf(m, qx - (cx - r) * HH);
    if (cx + r < GG - 1) m = fminf(m, (cx + r + 1) * HH - qx);
    if (cy - r > 0)      m = fminf(m, qy - (cy - r) * HH);
    if (cy + r < GG - 1) m = fminf(m, (cy + r + 1) * HH - qy);
    if (cz - r > 0)      m = fminf(m, qz - (cz - r) * HH);
    if (cz + r < GG - 1) m = fminf(m, (cz + r + 1) * HH - qz);
    return m * m;
}

// 4-NN insert tracking distances AND coordinates
#define INS4C(VAL, X, Y, Z)                                                   \
    do {                                                                      \
        if ((VAL) < d3) {                                                     \
            if ((VAL) < d2) {                                                 \
                d3 = d2; x3 = x2; y3 = y2; z3 = z2;                           \
                if ((VAL) < d1) {                                             \
                    d2 = d1; x2 = x1; y2 = y1; z2 = z1;                       \
                    if ((VAL) < d0) {                                         \
                        d1 = d0; x1 = x0; y1 = y0; z1 = z0;                   \
                        d0 = (VAL); x0 = (X); y0 = (Y); z0 = (Z);             \
                    } else { d1 = (VAL); x1 = (X); y1 = (Y); z1 = (Z); }      \
                } else { d2 = (VAL); x2 = (X); y2 = (Y); z2 = (Z); }          \
            } else { d3 = (VAL); x3 = (X); y3 = (Y); z3 = (Z); }              \
        }                                                                     \
    } while (0)

// ---------------- fused kernel: 1024 CTAs, role-split producers ----------------
// CTAs 0..255:   insert noisy share -> noisyCtr; wait noisyCtr==256; A; flag.
// CTAs 256..511: insert clean share -> cleanCtr.
// ALL CTAs:      B (8 warps x 1 query) after cleanCtr==256 && flag[parent].
__global__ __launch_bounds__(256, 4) void fused_kernel(
        const float* __restrict__ noisy,
        const float* __restrict__ clean,
        const int*   __restrict__ sidx,
        const float* __restrict__ Wf,
        const float* __restrict__ Wx,
        const float* __restrict__ Wc,
        float* __restrict__ out) {
    __shared__ float bd[CAP32];
    __shared__ int   bi[CAP32];
    __shared__ float cd[CAP2];
    __shared__ int   ci[CAP2];
    __shared__ float shp[4][3];
    __shared__ int   sh_cnt, sh_m;
    __shared__ unsigned long long sh_acc;
    int tid = threadIdx.x, lane = tid & 31, warp = tid >> 5;
    int cta = blockIdx.x;
    int* flags    = g_cnt + 2*BB*NCELLS;
    int* noisyCtr = flags + NPQ;
    int* cleanCtr = flags + NPQ + 1;

    if (cta < NPQ) {
        // ======== producer A: noisy insert share, then KNN-32 ========
        if (cta == 0 && tid == 0) { g_acc = 0ULL; g_done = 0u; }
        #pragma unroll
        for (int k = 0; k < 2; k++) {
            int i = cta*256 + tid + k*(NPQ*256);
            if (i < BB*NN) {
                int b = i / NN;
                float x = noisy[3*i], y = noisy[3*i+1], z = noisy[3*i+2];
                int c = b*NCELLS + cell_of(x, y, z);
                int pos = atomicAdd(&g_cnt[c], 1);
                if (pos < CAPC) g_slotN[c*CAPC + pos] = make_float4(x, y, z, 0.f);
            }
        }
        __threadfence();
        __syncthreads();
        if (tid == 0) {
            atomicAdd(noisyCtr, 1);
            while (atomicAdd(noisyCtr, 0) < NPQ) __nanosleep(128);
            __threadfence();
        }
        __syncthreads();

        int qid = cta;
        int b = qid >> 7, p = qid & 127;
        int gi = b*NN + sidx[p];
        float qx = noisy[3*gi], qy = noisy[3*gi+1], qz = noisy[3*gi+2];
        if (tid == 0) sh_cnt = 0;

        // phase 0: warps 0-3, one feature per lane
        if (warp < 4) {
            int f = warp*32 + lane;
            float ft = qx*Wf[f] + qy*Wf[FD+f] + qz*Wf[2*FD+f];
            float a0 = ft * Wc[3*f+0];
            float a1 = ft * Wc[3*f+1];
            float a2 = ft * Wc[3*f+2];
            for (int off = 16; off; off >>= 1) {
                a0 += __shfl_xor_sync(0xffffffffu, a0, off);
                a1 += __shfl_xor_sync(0xffffffffu, a1, off);
                a2 += __shfl_xor_sync(0xffffffffu, a2, off);
            }
            if (lane == 0) { shp[warp][0] = a0; shp[warp][1] = a1; shp[warp][2] = a2; }
        }
        __syncthreads();
        if (tid == 0) {
            g_q4[qid] = make_float4(qx, qy, qz, 0.f);
            g_c4[qid] = make_float4(shp[0][0]+shp[1][0]+shp[2][0]+shp[3][0],
                                    shp[0][1]+shp[1][1]+shp[2][1]+shp[3][1],
                                    shp[0][2]+shp[1][2]+shp[2][2]+shp[3][2], 0.f);
        }

        // phase 1: KNN-32 over noisy grid
        int qcx = min(max((int)(qx * GG), 0), GG-1);
        int qcy = min(max((int)(qy * GG), 0), GG-1);
        int qcz = min(max((int)(qz * GG), 0), GG-1);
        const int*    ncnt  = g_cnt   + b*NCELLS;
        const float4* nslot = g_slotN + (long)b*NCELLS*CAPC;

        {
            int side = 5, n = side*side*side;       // rings 0..2: 125 cells
            for (int t = tid; t < n; t += 256) {
                int dz = t/(side*side) - 2, rem = t%(side*side);
                int dy = rem/side - 2, dx = rem%side - 2;
                int cx = qcx+dx, cy = qcy+dy, cz = qcz+dz;
                if (cx < 0 || cx >= GG || cy < 0 || cy >= GG || cz < 0 || cz >= GG) continue;
                int c = (cz*GG + cy)*GG + cx;
                int e = min(ncnt[c], CAPC);
                int base = c*CAPC;
                for (int j = 0; j < e; j++) {
                    float4 pt = nslot[base + j];
                    float ddx = pt.x-qx, ddy = pt.y-qy, ddz = pt.z-qz;
                    float d = fmaf(ddx, ddx, fmaf(ddy, ddy, ddz*ddz));
                    int pos = atomicAdd(&sh_cnt, 1);
                    if (pos < CAP32) { bd[pos] = d; bi[pos] = base + j; }
                }
            }
        }
        __syncthreads();

        // merged compact+check loop
        int r = 2;
        int mfin;
        while (true) {
            float T = ring_T(qx, qy, qz, qcx, qcy, qcz, r);
            if (tid == 0) sh_m = 0;
            __syncthreads();
            int n_in = min(sh_cnt, CAP32);
            for (int j = tid; j < n_in; j += 256) {
                float dv = bd[j];
                if (dv < T) {
                    int pos = atomicAdd(&sh_m, 1);
                    if (pos < CAP2) { cd[pos] = dv; ci[pos] = bi[j]; }
                }
            }
            __syncthreads();
            mfin = sh_m;
            if (mfin >= KK || r >= 64) break;
            __syncthreads();
            r++;
            int side = 2*r+1, n = side*side*side;
            for (int t = tid; t < n; t += 256) {
                int dz = t/(side*side) - r, rem = t%(side*side);
                int dy = rem/side - r, dx = rem%side - r;
                if (max(abs(dx), max(abs(dy), abs(dz))) < r) continue;
                int cx = qcx+dx, cy = qcy+dy, cz = qcz+dz;
                if (cx < 0 || cx >= GG || cy < 0 || cy >= GG || cz < 0 || cz >= GG) continue;
                int cc = (cz*GG + cy)*GG + cx;
                int e = min(ncnt[cc], CAPC);
                int base = cc*CAPC;
                for (int j = 0; j < e; j++) {
                    float4 pt = nslot[base + j];
                    float ddx = pt.x-qx, ddy = pt.y-qy, ddz = pt.z-qz;
                    float d = fmaf(ddx, ddx, fmaf(ddy, ddy, ddz*ddz));
                    int pos = atomicAdd(&sh_cnt, 1);
                    if (pos < CAP32) { bd[pos] = d; bi[pos] = base + j; }
                }
            }
            __syncthreads();
        }

        // rank-select top-32
        if (mfin <= CAP2) {
            for (int i = tid; i < mfin; i += 256) {
                float di = cd[i];
                int ii = ci[i];
                int rank = 0;
                for (int j = 0; j < mfin; j++) {
                    float dj = cd[j];
                    rank += (dj < di) || (dj == di && ci[j] < ii);
                }
                if (rank < KK) {
                    float4 pp = nslot[ii];
                    g_f4[qid*KK + rank] = make_float4(pp.x, pp.y, pp.z, 0.f);
                }
            }
        } else {
            int n_in = min(sh_cnt, CAP32);
            for (int i = tid; i < n_in; i += 256) {
                float di = bd[i];
                int rank = 0;
                for (int j = 0; j < n_in; j++) {
                    float dj = bd[j];
                    rank += (dj < di) || (dj == di && j < i);
                }
                if (rank < KK) {
                    float4 pp = nslot[bi[i]];
                    g_f4[qid*KK + rank] = make_float4(pp.x, pp.y, pp.z, 0.f);
                }
            }
        }
        __threadfence();
        __syncthreads();
        if (tid == 0) atomicExch(&flags[qid], 1);   // release
    } else if (cta < 2*NPQ) {
        // ======== producer C (CTAs 256..511): clean insert share ========
        #pragma unroll
        for (int k = 0; k < 2; k++) {
            int i = (cta - NPQ)*256 + tid + k*(NPQ*256);
            if (i < BB*MM) {
                int b = i / MM;
                float x = clean[3*i], y = clean[3*i+1], z = clean[3*i+2];
                int c = b*NCELLS + cell_of(x, y, z);
                int pos = atomicAdd(&g_cnt[BB*NCELLS + c], 1);
                if (pos < CAPC) g_slotC[c*CAPC + pos] = make_float4(x, y, z, 0.f);
            }
        }
        __threadfence();
        __syncthreads();
        if (tid == 0) atomicAdd(cleanCtr, 1);
    }

    // ======== part B: all CTAs; 8 warps x 1 second-stage query ========
    int pq = cta >> 2;                        // parent first-stage query
    if (tid == 0) {
        sh_acc = 0ULL;
        while (atomicAdd(cleanCtr, 0) < NPQ) __nanosleep(128);
        while (atomicAdd(&flags[pq], 0) == 0) __nanosleep(64);
        __threadfence();                      // acquire
    }
    __syncthreads();

    int qi = cta*8 + warp;                    // 0..8191
    int b = qi >> 12;
    float4 f = __ldcg(&g_f4[qi]);
    float fx = f.x, fy = f.y, fz = f.z;
    int fcx = min(max((int)(fx * GG), 0), GG-1);
    int fcy = min(max((int)(fy * GG), 0), GG-1);
    int fcz = min(max((int)(fz * GG), 0), GG-1);
    const int*    ccnt  = g_cnt   + BB*NCELLS + b*NCELLS;
    const float4* cslot = g_slotC + (long)b*NCELLS*CAPC;

    float d0 = FINF, d1 = FINF, d2 = FINF, d3 = FINF;
    float x0=0.f,y0=0.f,z0=0.f, x1=0.f,y1=0.f,z1=0.f;
    float x2=0.f,y2=0.f,z2=0.f, x3=0.f,y3=0.f,z3=0.f;

    // rings 0..1: 27 cells, one per lane
    if (lane < 27) {
        int dz = lane/9 - 1, dy = (lane/3)%3 - 1, dx = lane%3 - 1;
        int cx = fcx+dx, cy = fcy+dy, cz = fcz+dz;
        if (cx >= 0 && cx < GG && cy >= 0 && cy < GG && cz >= 0 && cz < GG) {
            int c = (cz*GG + cy)*GG + cx;
            int e = min(ccnt[c], CAPC);
            int base = c*CAPC;
            for (int j = 0; j < e; j++) {
                float4 pt = cslot[base + j];
                float ddx = pt.x-fx, ddy = pt.y-fy, ddz = pt.z-fz;
                float t = fmaf(ddx, ddx, fmaf(ddy, ddy, ddz*ddz));
                INS4C(t, pt.x, pt.y, pt.z);
            }
        }
    }
    int rr = 1;
    while (true) {
        float T = ring_T(fx, fy, fz, fcx, fcy, fcz, rr);
        int c = (d0 < T) + (d1 < T) + (d2 < T) + (d3 < T);
        int tot = __reduce_add_sync(0xffffffffu, (unsigned)c);
        if (tot >= KC || rr >= 64) break;
        rr++;
        int side = 2*rr+1, n = side*side*side;
        for (int t = lane; t < n; t += 32) {
            int dz = t/(side*side) - rr, rem = t%(side*side);
            int dy = rem/side - rr, dx = rem%side - rr;
            if (max(abs(dx), max(abs(dy), abs(dz))) < rr) continue;
            int cx = fcx+dx, cy = fcy+dy, cz = fcz+dz;
            if (cx < 0 || cx >= GG || cy < 0 || cy >= GG || cz < 0 || cz >= GG) continue;
            int cc = (cz*GG + cy)*GG + cx;
            int e = min(ccnt[cc], CAPC);
            int base = cc*CAPC;
            for (int j = 0; j < e; j++) {
                float4 pt = cslot[base + j];
                float ddx = pt.x-fx, ddy = pt.y-fy, ddz = pt.z-fz;
                float t2 = fmaf(ddx, ddx, fmaf(ddy, ddy, ddz*ddz));
                INS4C(t2, pt.x, pt.y, pt.z);
            }
        }
    }

    // extract 4 mins across the warp; coords travel by shfl
    float sx = 0.f, sy = 0.f, sz = 0.f;
    for (int e4 = 0; e4 < KC; e4++) {
        float v = d0; int src = lane;
        #pragma unroll
        for (int off = 16; off; off >>= 1) {
            float vo = __shfl_xor_sync(0xffffffffu, v, off);
            int   so = __shfl_xor_sync(0xffffffffu, src, off);
            if (vo < v || (vo == v && so < src)) { v = vo; src = so; }
        }
        float wx_ = __shfl_sync(0xffffffffu, x0, src);
        float wy_ = __shfl_sync(0xffffffffu, y0, src);
        float wz_ = __shfl_sync(0xffffffffu, z0, src);
        if (lane == src) {
            d0 = d1; x0 = x1; y0 = y1; z0 = z1;
            d1 = d2; x1 = x2; y1 = y2; z1 = z2;
            d2 = d3; x2 = x3; y2 = y3; z2 = z3;
            d3 = FINF;
        }
        sx += wx_; sy += wy_; sz += wz_;
    }

    if (lane == 0) {
        float4 q4 = __ldcg(&g_q4[pq]);
        float4 c4 = __ldcg(&g_c4[pq]);
        float gx = 0.25f*sx - fx;
        float gy = 0.25f*sy - fy;
        float gz = 0.25f*sz - fz;
        float dx = fx - q4.x;
        float dy = fy - q4.y;
        float dz = fz - q4.z;
        float ex = c4.x + dx*Wx[0] + dy*Wx[3] + dz*Wx[6];
        float ey = c4.y + dx*Wx[1] + dy*Wx[4] + dz*Wx[7];
        float ez = c4.z + dx*Wx[2] + dy*Wx[5] + dz*Wx[8];
        float r0 = ex - gx, r1 = ey - gy, r2 = ez - gz;
        float term = fmaf(r0, r0, fmaf(r1, r1, r2*r2));
        unsigned long long q =
            (unsigned long long)__double2ll_rn((double)term * 4294967296.0);
        atomicAdd(&sh_acc, q);
    }
    __syncthreads();

    if (tid == 0) {
        atomicAdd(&g_acc, sh_acc);
        __threadfence();
        unsigned int old = atomicAdd(&g_done, 1u);
        if (old == NCTA_F - 1) {
            unsigned long long acc = atomicAdd(&g_acc, 0ULL);
            double sum = (double)acc * (1.0 / 4294967296.0);
            out[0] = (float)(sum * (0.5 / (0.01 * 8192.0)));
        }
    }
}

// ---------------- launch ----------------
extern "C" void kernel_launch(void* const* d_in, const int* in_sizes, int n_in,
                              void* d_out, int out_size) {
    const float* noisy = (const float*)d_in[0];
    const float* clean = (const float*)d_in[1];
    const int*   sidx  = (const int*)  d_in[2];
    const float* Wf    = (const float*)d_in[3];
    const float* Wx    = (const float*)d_in[4];
    const float* Wc    = (const float*)d_in[5];
    float* out = (float*)d_out;

    void* pCnt = nullptr;
    cudaGetSymbolAddress(&pCnt, g_cnt);
    cudaMemsetAsync(pCnt, 0, (2*BB*NCELLS + NPQ + 2)*sizeof(int), 0);

    fused_kernel<<<NCTA_F, 256>>>(noisy, clean, sidx, Wf, Wx, Wc, out);
}